// round 1
// baseline (speedup 1.0000x reference)
#include <cuda_runtime.h>
#include <math.h>

#define B_SZ   512
#define I_CAPS 1152
#define Q_SZ   8
#define O_CAPS 10
#define P_SZ   16
#define K_TOT  (I_CAPS * Q_SZ)   // 9216
#define N_TOT  (O_CAPS * P_SZ)   // 160

#define KSPLIT_S 36
#define KCHUNK_S (K_TOT / KSPLIT_S)   // 256
#define BSPLIT_G 2
#define BCHUNK_G (B_SZ / BSPLIT_G)    // 256

// ---------------- scratch (static device globals; no allocation) ----------------
__device__ float g_Wt[K_TOT * N_TOT];               // W transposed to [k][n], 5.9 MB
__device__ float g_b[I_CAPS * O_CAPS];              // routing logits
__device__ float g_c[I_CAPS * O_CAPS];              // softmax coefficients
__device__ float g_spart[KSPLIT_S][B_SZ * N_TOT];   // split-K partials of s, 11.8 MB
__device__ float g_v[B_SZ * N_TOT];                 // squashed output per iter
__device__ float g_Gpart[BSPLIT_G][K_TOT * N_TOT];  // split-K partials of G, 11.8 MB

// ---------------- init b = 0 ----------------
__global__ void init_b_kernel() {
    int t = blockIdx.x * 256 + threadIdx.x;
    if (t < I_CAPS * O_CAPS) g_b[t] = 0.0f;
}

// ---------------- Wt[k*160+n] = W[i,o,p,q],  k=i*8+q, n=o*16+p ----------------
__global__ void wt_kernel(const float* __restrict__ W) {
    int t = blockIdx.x * 256 + threadIdx.x;
    if (t >= K_TOT * N_TOT) return;
    int k = t / N_TOT, n = t - (t / N_TOT) * N_TOT;
    int i = k >> 3, q = k & 7, o = n >> 4, p = n & 15;
    g_Wt[t] = W[i * (O_CAPS * P_SZ * Q_SZ) + o * (P_SZ * Q_SZ) + p * Q_SZ + q];
}

// ---------------- c = softmax over i of b  (one warp per o) ----------------
__global__ void softmax_kernel() {
    int o = threadIdx.x >> 5;
    int lane = threadIdx.x & 31;
    float mx = -1e30f;
    for (int i = lane; i < I_CAPS; i += 32)
        mx = fmaxf(mx, g_b[i * O_CAPS + o]);
    #pragma unroll
    for (int off = 16; off; off >>= 1)
        mx = fmaxf(mx, __shfl_xor_sync(0xffffffffu, mx, off));
    float sum = 0.0f;
    for (int i = lane; i < I_CAPS; i += 32)
        sum += expf(g_b[i * O_CAPS + o] - mx);
    #pragma unroll
    for (int off = 16; off; off >>= 1)
        sum += __shfl_xor_sync(0xffffffffu, sum, off);
    float inv = 1.0f / sum;
    for (int i = lane; i < I_CAPS; i += 32)
        g_c[i * O_CAPS + o] = expf(g_b[i * O_CAPS + o] - mx) * inv;
}

// ---------------- s GEMM: s[m,n] = sum_k x[m,k] * (c ⊙ Wt)[k,n] ----------------
// grid (4, 36): 128-row tiles of M=512, 36 K-splits of 256. 256 thr, 8x10 microtile.
__global__ void __launch_bounds__(256) s_gemm_kernel(const float* __restrict__ x) {
    __shared__ float sx[8][132];
    __shared__ float sw[8][162];
    __shared__ float sc[32 * O_CAPS];

    const int t  = threadIdx.x;
    const int m0 = blockIdx.x * 128;
    const int k0 = blockIdx.y * KCHUNK_S;
    const int tr = t >> 4, tc = t & 15;

    // c slice for the 32 i-values of this K chunk (contiguous in g_c)
    for (int idx = t; idx < 32 * O_CAPS; idx += 256)
        sc[idx] = g_c[(k0 >> 3) * O_CAPS + idx];

    float acc[8][10];
    #pragma unroll
    for (int r = 0; r < 8; r++)
        #pragma unroll
        for (int j = 0; j < 10; j++) acc[r][j] = 0.0f;

    for (int stage = 0; stage < KCHUNK_S / 8; ++stage) {
        const int kb = k0 + stage * 8;
        __syncthreads();
        #pragma unroll
        for (int j = 0; j < 4; j++) {           // 1024 x-elems
            int e = t + 256 * j;
            int m = e >> 3, kk = e & 7;
            sx[kk][m] = x[(m0 + m) * K_TOT + kb + kk];
        }
        #pragma unroll
        for (int j = 0; j < 5; j++) {           // 1280 w-elems, fuse c
            int e = t + 256 * j;
            int kk = e / 160, n = e - kk * 160;
            sw[kk][n] = g_Wt[(kb + kk) * N_TOT + n] * sc[stage * O_CAPS + (n >> 4)];
        }
        __syncthreads();
        #pragma unroll
        for (int kk = 0; kk < 8; ++kk) {
            float xr[8], wr[10];
            #pragma unroll
            for (int r = 0; r < 8; r++)  xr[r] = sx[kk][tr + 16 * r];
            #pragma unroll
            for (int j = 0; j < 10; j++) wr[j] = sw[kk][tc + 16 * j];
            #pragma unroll
            for (int r = 0; r < 8; r++)
                #pragma unroll
                for (int j = 0; j < 10; j++)
                    acc[r][j] += xr[r] * wr[j];
        }
    }

    float* out = &g_spart[blockIdx.y][0];
    #pragma unroll
    for (int r = 0; r < 8; r++)
        #pragma unroll
        for (int j = 0; j < 10; j++)
            out[(m0 + tr + 16 * r) * N_TOT + tc + 16 * j] = acc[r][j];
}

// ---------------- reduce split-K, then squash -> g_v (and d_out on last iter) ----
__global__ void squash_kernel(float* __restrict__ out, int write_out) {
    int tid = blockIdx.x * 256 + threadIdx.x;   // < 81920
    float sv = 0.0f;
    #pragma unroll
    for (int sp = 0; sp < KSPLIT_S; ++sp) sv += g_spart[sp][tid];
    float sq = sv * sv;
    #pragma unroll
    for (int off = 8; off; off >>= 1)
        sq += __shfl_xor_sync(0xffffffffu, sq, off);   // reduce over the 16-lane p-group
    float norm = sqrtf(sq + 1e-8f);
    float vv = (sq / (1.0f + sq)) * (sv / norm);
    g_v[tid] = vv;
    if (write_out) out[tid] = vv;
}

// ---------------- G GEMM: G[k,n] = sum_b x[b,k] * v[b,n] ----------------
// grid (72, 2): 128-row tiles of K_TOT=9216, 2 b-splits of 256.
__global__ void __launch_bounds__(256) g_gemm_kernel(const float* __restrict__ x) {
    __shared__ float sxT[8][132];
    __shared__ float svm[8][162];

    const int t  = threadIdx.x;
    const int k0 = blockIdx.x * 128;
    const int b0 = blockIdx.y * BCHUNK_G;
    const int tr = t >> 4, tc = t & 15;

    float acc[8][10];
    #pragma unroll
    for (int r = 0; r < 8; r++)
        #pragma unroll
        for (int j = 0; j < 10; j++) acc[r][j] = 0.0f;

    for (int stage = 0; stage < BCHUNK_G / 8; ++stage) {
        const int bb0 = b0 + stage * 8;
        __syncthreads();
        #pragma unroll
        for (int j = 0; j < 4; j++) {           // 1024 = 8 b x 128 k, coalesced in k
            int e = t + 256 * j;
            int bb = e >> 7, kL = e & 127;
            sxT[bb][kL] = x[(bb0 + bb) * K_TOT + k0 + kL];
        }
        #pragma unroll
        for (int j = 0; j < 5; j++) {           // 1280 v-elems
            int e = t + 256 * j;
            int bb = e / 160, n = e - bb * 160;
            svm[bb][n] = g_v[(bb0 + bb) * N_TOT + n];
        }
        __syncthreads();
        #pragma unroll
        for (int bb = 0; bb < 8; ++bb) {
            float xr[8], vr[10];
            #pragma unroll
            for (int r = 0; r < 8; r++)  xr[r] = sxT[bb][tr + 16 * r];
            #pragma unroll
            for (int j = 0; j < 10; j++) vr[j] = svm[bb][tc + 16 * j];
            #pragma unroll
            for (int r = 0; r < 8; r++)
                #pragma unroll
                for (int j = 0; j < 10; j++)
                    acc[r][j] += xr[r] * vr[j];
        }
    }

    float* out = &g_Gpart[blockIdx.y][0];
    #pragma unroll
    for (int r = 0; r < 8; r++)
        #pragma unroll
        for (int j = 0; j < 10; j++)
            out[(k0 + tr + 16 * r) * N_TOT + tc + 16 * j] = acc[r][j];
}

// ---------------- b[i,o] += (1/512) * sum_{pq} Wt[k,n] * G[k,n] over 8x16 block ----
__global__ void b_update_kernel() {
    int w = (blockIdx.x * 256 + threadIdx.x) >> 5;  // (i,o) pair index, < 11520
    int lane = threadIdx.x & 31;
    if (w >= I_CAPS * O_CAPS) return;
    int i = w / O_CAPS, o = w - i * O_CAPS;
    int row = i * 8 + (lane >> 2);
    int col = o * 16 + (lane & 3) * 4;
    int base = row * N_TOT + col;
    float4 wv = *(const float4*)&g_Wt[base];
    float4 g0 = *(const float4*)&g_Gpart[0][base];
    float4 g1 = *(const float4*)&g_Gpart[1][base];
    float d = wv.x * (g0.x + g1.x) + wv.y * (g0.y + g1.y)
            + wv.z * (g0.z + g1.z) + wv.w * (g0.w + g1.w);
    #pragma unroll
    for (int off = 16; off; off >>= 1)
        d += __shfl_xor_sync(0xffffffffu, d, off);
    if (lane == 0) g_b[w] += d * (1.0f / (float)B_SZ);
}

// ---------------- launch ----------------
extern "C" void kernel_launch(void* const* d_in, const int* in_sizes, int n_in,
                              void* d_out, int out_size) {
    const float* x = (const float*)d_in[0];
    const float* W = (const float*)d_in[1];
    // defensive: identify operands by element count
    if (n_in >= 2 && in_sizes[0] == I_CAPS * O_CAPS * P_SZ * Q_SZ) {
        W = (const float*)d_in[0];
        x = (const float*)d_in[1];
    }
    float* out = (float*)d_out;

    init_b_kernel<<<(I_CAPS * O_CAPS + 255) / 256, 256>>>();
    wt_kernel<<<(K_TOT * N_TOT + 255) / 256, 256>>>(W);

    for (int it = 0; it < 3; ++it) {
        softmax_kernel<<<1, 32 * O_CAPS>>>();
        s_gemm_kernel<<<dim3(B_SZ / 128, KSPLIT_S), 256>>>(x);
        squash_kernel<<<(B_SZ * N_TOT) / 256, 256>>>(out, it == 2 ? 1 : 0);
        if (it < 2) {
            g_gemm_kernel<<<dim3(K_TOT / 128, BSPLIT_G), 256>>>(x);
            b_update_kernel<<<(I_CAPS * O_CAPS * 32 + 255) / 256, 256>>>();
        }
    }
}

// round 2
// speedup vs baseline: 1.5164x; 1.5164x over previous
#include <cuda_runtime.h>
#include <math.h>

#define B_SZ   512
#define I_CAPS 1152
#define Q_SZ   8
#define O_CAPS 10
#define P_SZ   16
#define K_TOT  (I_CAPS * Q_SZ)   // 9216
#define N_TOT  (O_CAPS * P_SZ)   // 160

#define KSPLIT_S 72
#define KCHUNK_S (K_TOT / KSPLIT_S)   // 128
#define BSPLIT_G 4
#define BCHUNK_G (B_SZ / BSPLIT_G)    // 128

typedef unsigned long long u64;

// ---------------- scratch (static device globals; no allocation) ----------------
__device__ float g_Wt[K_TOT * N_TOT];               // W transposed to [k][n]
__device__ float g_b[I_CAPS * O_CAPS];              // routing logits
__device__ float g_c[I_CAPS * O_CAPS];              // softmax coefficients
__device__ float g_spart[KSPLIT_S][B_SZ * N_TOT];   // split-K partials of s
__device__ float g_v[B_SZ * N_TOT];                 // squashed output per iter
__device__ float g_Gpart[BSPLIT_G][K_TOT * N_TOT];  // split-B partials of G

__device__ __forceinline__ void ffma2(u64 &d, u64 a, u64 b) {
    asm("fma.rn.f32x2 %0, %1, %2, %0;" : "+l"(d) : "l"(a), "l"(b));
}

// ---------------- Wt[k*160+n] = W[i,o,p,q], k=i*8+q, n=o*16+p; also zero b ----
__global__ void wt_kernel(const float* __restrict__ W) {
    int t = blockIdx.x * 256 + threadIdx.x;
    if (t < I_CAPS * O_CAPS) g_b[t] = 0.0f;
    if (t >= K_TOT * N_TOT) return;
    int k = t / N_TOT, n = t - k * N_TOT;
    int i = k >> 3, q = k & 7, o = n >> 4, p = n & 15;
    g_Wt[t] = W[i * (O_CAPS * P_SZ * Q_SZ) + o * (P_SZ * Q_SZ) + p * Q_SZ + q];
}

// ---------------- c = softmax over i of b  (one warp per o) ----------------
__global__ void softmax_kernel() {
    int o = threadIdx.x >> 5;
    int lane = threadIdx.x & 31;
    float mx = -1e30f;
    for (int i = lane; i < I_CAPS; i += 32)
        mx = fmaxf(mx, g_b[i * O_CAPS + o]);
    #pragma unroll
    for (int off = 16; off; off >>= 1)
        mx = fmaxf(mx, __shfl_xor_sync(0xffffffffu, mx, off));
    float sum = 0.0f;
    for (int i = lane; i < I_CAPS; i += 32)
        sum += expf(g_b[i * O_CAPS + o] - mx);
    #pragma unroll
    for (int off = 16; off; off >>= 1)
        sum += __shfl_xor_sync(0xffffffffu, sum, off);
    float inv = 1.0f / sum;
    for (int i = lane; i < I_CAPS; i += 32)
        g_c[i * O_CAPS + o] = expf(g_b[i * O_CAPS + o] - mx) * inv;
}

// ---------------- s GEMM: s[m,n] = sum_k x[m,k] * (c ⊙ Wt)[k,n] ----------------
// grid (4, 72). 128 M-rows x 160 N, K-chunk 128, double-buffered, f32x2 packed.
// Row pairs (m, m+64) in packed lanes; B-operand duplicated {w,w} in smem.
__global__ void __launch_bounds__(256, 2) s_gemm_kernel(const float* __restrict__ x) {
    __shared__ float2 sxp[2][8 * 65];    // [kk][m] pairs {row m, row m+64}
    __shared__ float2 swd[2][8 * 160];   // [kk][n] duplicated {w,w} (c-scaled)
    __shared__ float  sc[(KCHUNK_S / 8) * O_CAPS];   // 16 i-values x 10 o

    const int t  = threadIdx.x;
    const int m0 = blockIdx.x * 128;
    const int k0 = blockIdx.y * KCHUNK_S;
    const int tr = t >> 4, tc = t & 15;

    const int kkA = t & 7,  mA = t >> 3;                 // e = t
    const int kkB = (t + 256) & 7, mB = (t + 256) >> 3;  // e = t + 256

    for (int idx = t; idx < (KCHUNK_S / 8) * O_CAPS; idx += 256)
        sc[idx] = g_c[(k0 >> 3) * O_CAPS + idx];
    __syncthreads();   // sc ready before first stage load uses it

    u64 acc[4][10];
    #pragma unroll
    for (int r = 0; r < 4; r++)
        #pragma unroll
        for (int j = 0; j < 10; j++) acc[r][j] = 0ull;

    float xlo0, xhi0, xlo1, xhi1, wv[5];

    // prologue: load stage 0
    {
        const int kb = k0;
        xlo0 = x[(m0 + mA) * K_TOT + kb + kkA];
        xhi0 = x[(m0 + mA + 64) * K_TOT + kb + kkA];
        xlo1 = x[(m0 + mB) * K_TOT + kb + kkB];
        xhi1 = x[(m0 + mB + 64) * K_TOT + kb + kkB];
        #pragma unroll
        for (int j = 0; j < 5; j++) {
            int e = t + 256 * j;
            int kk = e / 160, n = e - kk * 160;
            wv[j] = g_Wt[(kb + kk) * N_TOT + n] * sc[0 * O_CAPS + (n >> 4)];
        }
        sxp[0][kkA * 65 + mA] = make_float2(xlo0, xhi0);
        sxp[0][kkB * 65 + mB] = make_float2(xlo1, xhi1);
        #pragma unroll
        for (int j = 0; j < 5; j++) {
            int e = t + 256 * j;
            int kk = e / 160, n = e - kk * 160;
            swd[0][kk * 160 + n] = make_float2(wv[j], wv[j]);
        }
    }
    __syncthreads();

    for (int s = 0; s < KCHUNK_S / 8; ++s) {
        const int cur = s & 1;
        // prefetch next stage into regs
        if (s < KCHUNK_S / 8 - 1) {
            const int kb = k0 + (s + 1) * 8;
            xlo0 = x[(m0 + mA) * K_TOT + kb + kkA];
            xhi0 = x[(m0 + mA + 64) * K_TOT + kb + kkA];
            xlo1 = x[(m0 + mB) * K_TOT + kb + kkB];
            xhi1 = x[(m0 + mB + 64) * K_TOT + kb + kkB];
            #pragma unroll
            for (int j = 0; j < 5; j++) {
                int e = t + 256 * j;
                int kk = e / 160, n = e - kk * 160;
                wv[j] = g_Wt[(kb + kk) * N_TOT + n] * sc[(s + 1) * O_CAPS + (n >> 4)];
            }
        }
        // compute current stage
        {
            const float2* xb = sxp[cur];
            const float2* wb = swd[cur];
            #pragma unroll
            for (int kk = 0; kk < 8; ++kk) {
                u64 xp[4];
                #pragma unroll
                for (int r = 0; r < 4; r++)
                    xp[r] = *(const u64*)&xb[kk * 65 + tr + 16 * r];
                #pragma unroll
                for (int h = 0; h < 2; h++) {
                    u64 wd[5];
                    #pragma unroll
                    for (int j = 0; j < 5; j++)
                        wd[j] = *(const u64*)&wb[kk * 160 + tc + 16 * (h * 5 + j)];
                    #pragma unroll
                    for (int r = 0; r < 4; r++)
                        #pragma unroll
                        for (int j = 0; j < 5; j++)
                            ffma2(acc[r][h * 5 + j], xp[r], wd[j]);
                }
            }
        }
        // store next stage
        if (s < KCHUNK_S / 8 - 1) {
            const int nxt = cur ^ 1;
            sxp[nxt][kkA * 65 + mA] = make_float2(xlo0, xhi0);
            sxp[nxt][kkB * 65 + mB] = make_float2(xlo1, xhi1);
            #pragma unroll
            for (int j = 0; j < 5; j++) {
                int e = t + 256 * j;
                int kk = e / 160, n = e - kk * 160;
                swd[nxt][kk * 160 + n] = make_float2(wv[j], wv[j]);
            }
        }
        __syncthreads();
    }

    float* out = &g_spart[blockIdx.y][0];
    #pragma unroll
    for (int r = 0; r < 4; r++)
        #pragma unroll
        for (int j = 0; j < 10; j++) {
            u64 a = acc[r][j];
            float lo = __uint_as_float((unsigned)a);
            float hi = __uint_as_float((unsigned)(a >> 32));
            int col = tc + 16 * j;
            out[(m0 + tr + 16 * r) * N_TOT + col] = lo;
            out[(m0 + tr + 16 * r + 64) * N_TOT + col] = hi;
        }
}

// ---------------- reduce split-K, then squash -> g_v (and d_out on last iter) ----
__global__ void squash_kernel(float* __restrict__ out, int write_out) {
    int tid = blockIdx.x * 256 + threadIdx.x;   // < 81920
    float sv = 0.0f;
    #pragma unroll 8
    for (int sp = 0; sp < KSPLIT_S; ++sp) sv += g_spart[sp][tid];
    float sq = sv * sv;
    #pragma unroll
    for (int off = 8; off; off >>= 1)
        sq += __shfl_xor_sync(0xffffffffu, sq, off);   // reduce over the 16-lane p-group
    float norm = sqrtf(sq + 1e-8f);
    float vv = (sq / (1.0f + sq)) * (sv / norm);
    g_v[tid] = vv;
    if (write_out) out[tid] = vv;
}

// ---------------- G GEMM: G[k,n] = sum_b x[b,k] * v[b,n] ----------------
// grid (72, 4). 128 k-rows x 160 N, b-chunk 128, same packed scheme.
__global__ void __launch_bounds__(256, 2) g_gemm_kernel(const float* __restrict__ x) {
    __shared__ float2 sxp[2][8 * 65];    // [bb][m] pairs {k0+m, k0+m+64}
    __shared__ float2 svd[2][8 * 160];   // [bb][n] duplicated {v,v}

    const int t  = threadIdx.x;
    const int k0 = blockIdx.x * 128;
    const int b0 = blockIdx.y * BCHUNK_G;
    const int tr = t >> 4, tc = t & 15;

    const int mA = t & 63,        bbA = t >> 6;           // e = t      (bb 0..3)
    const int mB = (t + 256) & 63, bbB = (t + 256) >> 6;  // e = t+256  (bb 4..7)

    u64 acc[4][10];
    #pragma unroll
    for (int r = 0; r < 4; r++)
        #pragma unroll
        for (int j = 0; j < 10; j++) acc[r][j] = 0ull;

    float xlo0, xhi0, xlo1, xhi1, wv[5];

    // prologue: stage 0
    {
        const int bb0 = b0;
        xlo0 = x[(bb0 + bbA) * K_TOT + k0 + mA];
        xhi0 = x[(bb0 + bbA) * K_TOT + k0 + mA + 64];
        xlo1 = x[(bb0 + bbB) * K_TOT + k0 + mB];
        xhi1 = x[(bb0 + bbB) * K_TOT + k0 + mB + 64];
        #pragma unroll
        for (int j = 0; j < 5; j++) {
            int e = t + 256 * j;
            int bb = e / 160, n = e - bb * 160;
            wv[j] = g_v[(bb0 + bb) * N_TOT + n];
        }
        sxp[0][bbA * 65 + mA] = make_float2(xlo0, xhi0);
        sxp[0][bbB * 65 + mB] = make_float2(xlo1, xhi1);
        #pragma unroll
        for (int j = 0; j < 5; j++) {
            int e = t + 256 * j;
            int bb = e / 160, n = e - bb * 160;
            svd[0][bb * 160 + n] = make_float2(wv[j], wv[j]);
        }
    }
    __syncthreads();

    for (int s = 0; s < BCHUNK_G / 8; ++s) {
        const int cur = s & 1;
        if (s < BCHUNK_G / 8 - 1) {
            const int bb0 = b0 + (s + 1) * 8;
            xlo0 = x[(bb0 + bbA) * K_TOT + k0 + mA];
            xhi0 = x[(bb0 + bbA) * K_TOT + k0 + mA + 64];
            xlo1 = x[(bb0 + bbB) * K_TOT + k0 + mB];
            xhi1 = x[(bb0 + bbB) * K_TOT + k0 + mB + 64];
            #pragma unroll
            for (int j = 0; j < 5; j++) {
                int e = t + 256 * j;
                int bb = e / 160, n = e - bb * 160;
                wv[j] = g_v[(bb0 + bb) * N_TOT + n];
            }
        }
        {
            const float2* xb = sxp[cur];
            const float2* vb = svd[cur];
            #pragma unroll
            for (int bb = 0; bb < 8; ++bb) {
                u64 xp[4];
                #pragma unroll
                for (int r = 0; r < 4; r++)
                    xp[r] = *(const u64*)&xb[bb * 65 + tr + 16 * r];
                #pragma unroll
                for (int h = 0; h < 2; h++) {
                    u64 wd[5];
                    #pragma unroll
                    for (int j = 0; j < 5; j++)
                        wd[j] = *(const u64*)&vb[bb * 160 + tc + 16 * (h * 5 + j)];
                    #pragma unroll
                    for (int r = 0; r < 4; r++)
                        #pragma unroll
                        for (int j = 0; j < 5; j++)
                            ffma2(acc[r][h * 5 + j], xp[r], wd[j]);
                }
            }
        }
        if (s < BCHUNK_G / 8 - 1) {
            const int nxt = cur ^ 1;
            sxp[nxt][bbA * 65 + mA] = make_float2(xlo0, xhi0);
            sxp[nxt][bbB * 65 + mB] = make_float2(xlo1, xhi1);
            #pragma unroll
            for (int j = 0; j < 5; j++) {
                int e = t + 256 * j;
                int bb = e / 160, n = e - bb * 160;
                svd[nxt][bb * 160 + n] = make_float2(wv[j], wv[j]);
            }
        }
        __syncthreads();
    }

    float* out = &g_Gpart[blockIdx.y][0];
    #pragma unroll
    for (int r = 0; r < 4; r++)
        #pragma unroll
        for (int j = 0; j < 10; j++) {
            u64 a = acc[r][j];
            float lo = __uint_as_float((unsigned)a);
            float hi = __uint_as_float((unsigned)(a >> 32));
            int col = tc + 16 * j;
            out[(k0 + tr + 16 * r) * N_TOT + col] = lo;
            out[(k0 + tr + 16 * r + 64) * N_TOT + col] = hi;
        }
}

// ---------------- b[i,o] += (1/512) * sum_{pq} Wt[k,n] * G[k,n] over 8x16 block ----
__global__ void b_update_kernel() {
    int w = (blockIdx.x * 256 + threadIdx.x) >> 5;  // (i,o) pair index, < 11520
    int lane = threadIdx.x & 31;
    if (w >= I_CAPS * O_CAPS) return;
    int i = w / O_CAPS, o = w - i * O_CAPS;
    int row = i * 8 + (lane >> 2);
    int col = o * 16 + (lane & 3) * 4;
    int base = row * N_TOT + col;
    float4 wv = *(const float4*)&g_Wt[base];
    float4 g0 = *(const float4*)&g_Gpart[0][base];
    float4 g1 = *(const float4*)&g_Gpart[1][base];
    float4 g2 = *(const float4*)&g_Gpart[2][base];
    float4 g3 = *(const float4*)&g_Gpart[3][base];
    float d = wv.x * (g0.x + g1.x + g2.x + g3.x)
            + wv.y * (g0.y + g1.y + g2.y + g3.y)
            + wv.z * (g0.z + g1.z + g2.z + g3.z)
            + wv.w * (g0.w + g1.w + g2.w + g3.w);
    #pragma unroll
    for (int off = 16; off; off >>= 1)
        d += __shfl_xor_sync(0xffffffffu, d, off);
    if (lane == 0) g_b[w] += d * (1.0f / (float)B_SZ);
}

// ---------------- launch ----------------
extern "C" void kernel_launch(void* const* d_in, const int* in_sizes, int n_in,
                              void* d_out, int out_size) {
    const float* x = (const float*)d_in[0];
    const float* W = (const float*)d_in[1];
    if (n_in >= 2 && in_sizes[0] == I_CAPS * O_CAPS * P_SZ * Q_SZ) {
        W = (const float*)d_in[0];
        x = (const float*)d_in[1];
    }
    float* out = (float*)d_out;

    wt_kernel<<<(K_TOT * N_TOT + 255) / 256, 256>>>(W);

    for (int it = 0; it < 3; ++it) {
        softmax_kernel<<<1, 32 * O_CAPS>>>();
        s_gemm_kernel<<<dim3(B_SZ / 128, KSPLIT_S), 256>>>(x);
        squash_kernel<<<(B_SZ * N_TOT) / 256, 256>>>(out, it == 2 ? 1 : 0);
        if (it < 2) {
            g_gemm_kernel<<<dim3(K_TOT / 128, BSPLIT_G), 256>>>(x);
            b_update_kernel<<<(I_CAPS * O_CAPS * 32 + 255) / 256, 256>>>();
        }
    }
}